// round 3
// baseline (speedup 1.0000x reference)
#include <cuda_runtime.h>
#include <math.h>

// ----------------------------------------------------------------------------
// Strict2_5DLoss: triangle-assignment detection loss, 3 FPN levels.
// B=8, Ng=32, K=64, ETA=3, POS_W=1.2, strides {8,16,32}, grids {256,128,64}.
//
// Strategy: positives are confined to triangle bbox +/- ETA. One block per
// (b, g, level) scans only that bbox, collects positive (dist, hw) pairs in
// shared memory, rank-selects the 64 smallest (tie-break: lower hw index,
// matching jax.lax.top_k stability), and accumulates reg/cls/pos directly.
// A dense pass computes objectness BCE + pos_now over all 688128 cells.
// ----------------------------------------------------------------------------

#define CAP 4096
#define NT  256
#define TOTAL_CELLS 688128   // 8*(65536+16384+4096)

__device__ double g_reg_s, g_cls_s, g_obj_s, g_pos, g_posnow;
__device__ __align__(16) unsigned char g_mark[TOTAL_CELLS];

__device__ __forceinline__ float seg_dist_f(float px, float py,
                                            float x1, float y1,
                                            float x2, float y2) {
    float vx = x2 - x1, vy = y2 - y1;
    float wx = px - x1, wy = py - y1;
    float t = (wx * vx + wy * vy) / (vx * vx + vy * vy + 1e-9f);
    t = fminf(fmaxf(t, 0.0f), 1.0f);
    float dx = px - (x1 + t * vx);
    float dy = py - (y1 + t * vy);
    return sqrtf(dx * dx + dy * dy + 1e-12f);
}

// softplus(x) = max(x,0) + log1p(exp(-|x|))   (matches jax.nn.softplus)
__device__ __forceinline__ float softplusf(float x) {
    return fmaxf(x, 0.0f) + log1pf(expf(-fabsf(x)));
}

__global__ void zero_kernel() {
    int i = blockIdx.x * blockDim.x + threadIdx.x;
    if (i < TOTAL_CELLS / 16)
        reinterpret_cast<uint4*>(g_mark)[i] = make_uint4(0, 0, 0, 0);
    if (i == 0) {
        g_reg_s = 0.0; g_cls_s = 0.0; g_obj_s = 0.0;
        g_pos = 0.0;  g_posnow = 0.0;
    }
}

__global__ void __launch_bounds__(NT)
pair_kernel(const float* __restrict__ reg0, const float* __restrict__ cls0,
            const float* __restrict__ reg1, const float* __restrict__ cls1,
            const float* __restrict__ reg2, const float* __restrict__ cls2,
            const float* __restrict__ gt) {
    __shared__ float  s_d[CAP];
    __shared__ int    s_i[CAP];
    __shared__ int    s_count;
    __shared__ double s_red[NT];

    const int lvl = blockIdx.y;
    const int b   = blockIdx.x >> 5;
    const int g   = blockIdx.x & 31;
    const int Ws  = 256 >> lvl;
    const int HW  = Ws * Ws;
    const float st = (float)(8 << lvl);

    const float* reg = (lvl == 0) ? reg0 : (lvl == 1) ? reg1 : reg2;
    const float* cls = (lvl == 0) ? cls0 : (lvl == 1) ? cls1 : cls2;
    const int markBase = ((lvl == 0) ? 0 : (lvl == 1) ? 524288 : 655360) + b * HW;

    const float* gp = gt + (size_t)(b * 32 + g) * 6;
    const float Ax = gp[0], Ay = gp[1];
    const float Bx = gp[2], By = gp[3];
    const float Cx = gp[4], Cy = gp[5];

    if (threadIdx.x == 0) s_count = 0;
    __syncthreads();

    // bbox of triangle expanded by ETA=3; over-cover by one cell (harmless).
    float minx = fminf(Ax, fminf(Bx, Cx)) - 3.0f;
    float maxx = fmaxf(Ax, fmaxf(Bx, Cx)) + 3.0f;
    float miny = fminf(Ay, fminf(By, Cy)) - 3.0f;
    float maxy = fmaxf(Ay, fmaxf(By, Cy)) + 3.0f;
    int ix0 = max(0,      (int)floorf(minx / st - 0.5f));
    int ix1 = min(Ws - 1, (int)floorf(maxx / st - 0.5f) + 1);
    int iy0 = max(0,      (int)floorf(miny / st - 0.5f));
    int iy1 = min(Ws - 1, (int)floorf(maxy / st - 0.5f) + 1);
    int nx = ix1 - ix0 + 1; if (nx < 0) nx = 0;
    int ny = iy1 - iy0 + 1; if (ny < 0) ny = 0;
    const int tot = nx * ny;

    for (int c = threadIdx.x; c < tot; c += NT) {
        int ix = ix0 + c % nx;
        int iy = iy0 + c / nx;
        float px = (ix + 0.5f) * st;
        float py = (iy + 0.5f) * st;
        // sign(p1,p2,p3) = (x1-x3)(y2-y3) - (x2-x3)(y1-y3)
        float d1 = (px - Bx) * (Ay - By) - (Ax - Bx) * (py - By);
        float d2 = (px - Cx) * (By - Cy) - (Bx - Cx) * (py - Cy);
        float d3 = (px - Ax) * (Cy - Ay) - (Cx - Ax) * (py - Ay);
        bool hneg = (d1 < 0.0f) || (d2 < 0.0f) || (d3 < 0.0f);
        bool hpos = (d1 > 0.0f) || (d2 > 0.0f) || (d3 > 0.0f);
        bool inside = !(hneg && hpos);
        float dist = fminf(seg_dist_f(px, py, Ax, Ay, Bx, By),
                     fminf(seg_dist_f(px, py, Bx, By, Cx, Cy),
                           seg_dist_f(px, py, Cx, Cy, Ax, Ay)));
        if (inside || dist <= 3.0f) {
            int slot = atomicAdd(&s_count, 1);
            if (slot < CAP) { s_d[slot] = dist; s_i[slot] = iy * Ws + ix; }
        }
    }
    __syncthreads();
    const int count = min(s_count, CAP);

    double regAcc = 0.0, clsAcc = 0.0;
    int nv = 0;
    const float inv = 1.0f / st;  // strides are powers of two: exact

    for (int e = threadIdx.x; e < count; e += NT) {
        const float de = s_d[e];
        const int   ie = s_i[e];
        bool sel = true;
        if (count > 64) {
            int rank = 0;
            for (int j = 0; j < count; j++) {
                float dj = s_d[j];
                rank += (dj < de) || (dj == de && s_i[j] < ie);
            }
            sel = (rank < 64);
        }
        if (sel) {
            nv++;
            g_mark[markBase + ie] = 1;
            clsAcc += (double)softplusf(-cls[(size_t)b * HW + ie]);

            int ix = ie % Ws, iy = ie / Ws;
            float ax = (ix + 0.5f) * st;
            float ay = (iy + 0.5f) * st;
            float g0x = (Ax - ax) * inv, g0y = (Ay - ay) * inv;
            float g1x = (Bx - ax) * inv, g1y = (By - ay) * inv;
            float g2x = (Cx - ax) * inv, g2y = (Cy - ay) * inv;

            const float* rb = reg + (size_t)b * 6 * HW + ie;
            float p0x = fminf(fmaxf(rb[0],            -64.0f), 64.0f);
            float p0y = fminf(fmaxf(rb[(size_t)HW],   -64.0f), 64.0f);
            float p1x = fminf(fmaxf(rb[(size_t)2*HW], -64.0f), 64.0f);
            float p1y = fminf(fmaxf(rb[(size_t)3*HW], -64.0f), 64.0f);
            float p2x = fminf(fmaxf(rb[(size_t)4*HW], -64.0f), 64.0f);
            float p2y = fminf(fmaxf(rb[(size_t)5*HW], -64.0f), 64.0f);

            float p0 = (p0x - g0x) * (p0x - g0x) + (p0y - g0y) * (p0y - g0y);
            float d11 = sqrtf((p1x - g1x) * (p1x - g1x) + (p1y - g1y) * (p1y - g1y));
            float d12 = sqrtf((p1x - g2x) * (p1x - g2x) + (p1y - g2y) * (p1y - g2y));
            float d21 = sqrtf((p2x - g1x) * (p2x - g1x) + (p2y - g1y) * (p2y - g1y));
            float d22 = sqrtf((p2x - g2x) * (p2x - g2x) + (p2y - g2y) * (p2y - g2y));
            float cd = fminf(d11, d12) + fminf(d21, d22)
                     + fminf(d11, d21) + fminf(d12, d22);
            regAcc += (double)(p0 + cd);
        }
    }

    // block-reduce three accumulators, one atomic each per block
    s_red[threadIdx.x] = regAcc; __syncthreads();
    for (int o = NT / 2; o > 0; o >>= 1) {
        if (threadIdx.x < o) s_red[threadIdx.x] += s_red[threadIdx.x + o];
        __syncthreads();
    }
    if (threadIdx.x == 0) atomicAdd(&g_reg_s, s_red[0]);
    __syncthreads();

    s_red[threadIdx.x] = clsAcc; __syncthreads();
    for (int o = NT / 2; o > 0; o >>= 1) {
        if (threadIdx.x < o) s_red[threadIdx.x] += s_red[threadIdx.x + o];
        __syncthreads();
    }
    if (threadIdx.x == 0) atomicAdd(&g_cls_s, s_red[0]);
    __syncthreads();

    s_red[threadIdx.x] = (double)nv; __syncthreads();
    for (int o = NT / 2; o > 0; o >>= 1) {
        if (threadIdx.x < o) s_red[threadIdx.x] += s_red[threadIdx.x + o];
        __syncthreads();
    }
    if (threadIdx.x == 0) atomicAdd(&g_pos, s_red[0]);
}

__global__ void __launch_bounds__(NT)
obj_kernel(const float* __restrict__ obj0,
           const float* __restrict__ obj1,
           const float* __restrict__ obj2) {
    __shared__ double s_red[NT];
    double acc = 0.0, pn = 0.0;

    for (int i = blockIdx.x * NT + threadIdx.x; i < TOTAL_CELLS;
         i += gridDim.x * NT) {
        float x;
        if (i < 524288)      x = obj0[i];
        else if (i < 655360) x = obj1[i - 524288];
        else                 x = obj2[i - 655360];
        float l1p = log1pf(expf(-fabsf(x)));
        if (g_mark[i]) {
            acc += (double)(1.2f * (fmaxf(-x, 0.0f) + l1p));  // POS_W * softplus(-x)
            pn  += 1.0;
        } else {
            acc += (double)(fmaxf(x, 0.0f) + l1p);            // softplus(x)
        }
    }

    s_red[threadIdx.x] = acc; __syncthreads();
    for (int o = NT / 2; o > 0; o >>= 1) {
        if (threadIdx.x < o) s_red[threadIdx.x] += s_red[threadIdx.x + o];
        __syncthreads();
    }
    if (threadIdx.x == 0) atomicAdd(&g_obj_s, s_red[0]);
    __syncthreads();

    s_red[threadIdx.x] = pn; __syncthreads();
    for (int o = NT / 2; o > 0; o >>= 1) {
        if (threadIdx.x < o) s_red[threadIdx.x] += s_red[threadIdx.x + o];
        __syncthreads();
    }
    if (threadIdx.x == 0) atomicAdd(&g_posnow, s_red[0]);
}

__global__ void final_kernel(float* out) {
    double pos_eps = fmax(g_pos, 1.0);
    double neg = fmax((double)TOTAL_CELLS - g_posnow, 1.0);
    double total = g_reg_s / pos_eps
                 + g_obj_s / (pos_eps + neg)
                 + g_cls_s / pos_eps;
    float t = (float)total;
    out[0] = isfinite(t) ? t : 0.0f;
}

extern "C" void kernel_launch(void* const* d_in, const int* in_sizes, int n_in,
                              void* d_out, int out_size) {
    (void)in_sizes; (void)n_in; (void)out_size;
    const float* reg0 = (const float*)d_in[0];
    const float* obj0 = (const float*)d_in[1];
    const float* cls0 = (const float*)d_in[2];
    const float* reg1 = (const float*)d_in[3];
    const float* obj1 = (const float*)d_in[4];
    const float* cls1 = (const float*)d_in[5];
    const float* reg2 = (const float*)d_in[6];
    const float* obj2 = (const float*)d_in[7];
    const float* cls2 = (const float*)d_in[8];
    const float* gt   = (const float*)d_in[9];

    zero_kernel<<<(TOTAL_CELLS / 16 + NT - 1) / NT, NT>>>();
    pair_kernel<<<dim3(256, 3), NT>>>(reg0, cls0, reg1, cls1, reg2, cls2, gt);
    obj_kernel<<<512, NT>>>(obj0, obj1, obj2);
    final_kernel<<<1, 1>>>((float*)d_out);
}

// round 4
// speedup vs baseline: 1.1132x; 1.1132x over previous
#include <cuda_runtime.h>
#include <math.h>

// ----------------------------------------------------------------------------
// Strict2_5DLoss — single persistent kernel.
// B=8, Ng=32, K=64, ETA=3, POS_W=1.2, strides {8,16,32}, grids {256,128,64}.
//
// Phase 1 (all blocks, no ordering needed):
//   - dynamic (b,g,lvl) pair tasks: bbox scan -> positives in smem -> rank
//     top-64 select -> reg/cls/pos accumulation; obj handled as a correction
//     (POS_W*sp(-x) - sp(x)) applied once per unique cell via atomicOr dedup.
//   - dense obj baseline: sum softplus(x) over all 688128 cells.
// Grid barrier. Block 0 reduces per-block partials and writes the scalar;
// other blocks clear the dedup bitmask. Exit barrier resets counters so the
// captured graph replays identically.
// ----------------------------------------------------------------------------

#define NT   256
#define GRID 296
#define CAP  4096
#define NTASK 768
#define TOTAL_CELLS 688128          // 8*(65536+16384+4096)
#define NBITS (TOTAL_CELLS / 32)    // 21504 words

__device__ int g_task, g_arrive, g_exit;
__device__ unsigned g_bits[NBITS];          // zero-init at load; cleared each run
__device__ double g_part[GRID][5];          // reg, cls, obj, pos, posnow

__device__ __forceinline__ float seg_dist_f(float px, float py,
                                            float x1, float y1,
                                            float x2, float y2) {
    float vx = x2 - x1, vy = y2 - y1;
    float wx = px - x1, wy = py - y1;
    float t = (wx * vx + wy * vy) / (vx * vx + vy * vy + 1e-9f);
    t = fminf(fmaxf(t, 0.0f), 1.0f);
    float dx = px - (x1 + t * vx);
    float dy = py - (y1 + t * vy);
    return sqrtf(dx * dx + dy * dy + 1e-12f);
}

// softplus(x) = max(x,0) + log1p(exp(-|x|))   (matches jax.nn.softplus)
__device__ __forceinline__ float softplusf(float x) {
    return fmaxf(x, 0.0f) + log1pf(expf(-fabsf(x)));
}

__global__ void __launch_bounds__(NT, 2)
fused_kernel(const float* __restrict__ reg0, const float* __restrict__ obj0,
             const float* __restrict__ cls0,
             const float* __restrict__ reg1, const float* __restrict__ obj1,
             const float* __restrict__ cls1,
             const float* __restrict__ reg2, const float* __restrict__ obj2,
             const float* __restrict__ cls2,
             const float* __restrict__ gt, float* __restrict__ out) {
    __shared__ float  s_d[CAP];
    __shared__ int    s_i[CAP];
    __shared__ int    s_task, s_count;
    __shared__ double s_red[NT];
    __shared__ double s_tot[5];

    const int tid = threadIdx.x;
    const int bid = blockIdx.x;

    double acc[5];   // 0:reg 1:cls 2:obj 3:pos 4:posnow
#pragma unroll
    for (int c = 0; c < 5; c++) acc[c] = 0.0;

    // ---------------- Phase 1a: dynamic pair tasks ----------------
    for (;;) {
        if (tid == 0) { s_task = atomicAdd(&g_task, 1); s_count = 0; }
        __syncthreads();
        const int t = s_task;
        if (t >= NTASK) break;

        const int lvl = t % 3;
        const int p   = t / 3;
        const int b   = p >> 5;
        const int g   = p & 31;
        const int Ws  = 256 >> lvl;
        const int HW  = Ws * Ws;
        const float st = (float)(8 << lvl);

        const float* reg = (lvl == 0) ? reg0 : (lvl == 1) ? reg1 : reg2;
        const float* cls = (lvl == 0) ? cls0 : (lvl == 1) ? cls1 : cls2;
        const float* obj = (lvl == 0) ? obj0 : (lvl == 1) ? obj1 : obj2;
        const int markBase =
            ((lvl == 0) ? 0 : (lvl == 1) ? 524288 : 655360) + b * HW;

        const float* gp = gt + (size_t)(b * 32 + g) * 6;
        const float Ax = gp[0], Ay = gp[1];
        const float Bx = gp[2], By = gp[3];
        const float Cx = gp[4], Cy = gp[5];

        // bbox of triangle expanded by ETA=3; over-cover by one cell.
        float minx = fminf(Ax, fminf(Bx, Cx)) - 3.0f;
        float maxx = fmaxf(Ax, fmaxf(Bx, Cx)) + 3.0f;
        float miny = fminf(Ay, fminf(By, Cy)) - 3.0f;
        float maxy = fmaxf(Ay, fmaxf(By, Cy)) + 3.0f;
        int ix0 = max(0,      (int)floorf(minx / st - 0.5f));
        int ix1 = min(Ws - 1, (int)floorf(maxx / st - 0.5f) + 1);
        int iy0 = max(0,      (int)floorf(miny / st - 0.5f));
        int iy1 = min(Ws - 1, (int)floorf(maxy / st - 0.5f) + 1);
        int nx = ix1 - ix0 + 1; if (nx < 0) nx = 0;
        int ny = iy1 - iy0 + 1; if (ny < 0) ny = 0;
        const int tot = nx * ny;

        for (int c = tid; c < tot; c += NT) {
            int ix = ix0 + c % nx;
            int iy = iy0 + c / nx;
            float px = (ix + 0.5f) * st;
            float py = (iy + 0.5f) * st;
            float d1 = (px - Bx) * (Ay - By) - (Ax - Bx) * (py - By);
            float d2 = (px - Cx) * (By - Cy) - (Bx - Cx) * (py - Cy);
            float d3 = (px - Ax) * (Cy - Ay) - (Cx - Ax) * (py - Ay);
            bool hneg = (d1 < 0.0f) || (d2 < 0.0f) || (d3 < 0.0f);
            bool hpos = (d1 > 0.0f) || (d2 > 0.0f) || (d3 > 0.0f);
            bool inside = !(hneg && hpos);
            float dist = fminf(seg_dist_f(px, py, Ax, Ay, Bx, By),
                         fminf(seg_dist_f(px, py, Bx, By, Cx, Cy),
                               seg_dist_f(px, py, Cx, Cy, Ax, Ay)));
            if (inside || dist <= 3.0f) {
                int slot = atomicAdd(&s_count, 1);
                if (slot < CAP) { s_d[slot] = dist; s_i[slot] = iy * Ws + ix; }
            }
        }
        __syncthreads();
        const int count = min(s_count, CAP);
        const float inv = 1.0f / st;   // power-of-two stride: exact

        for (int e = tid; e < count; e += NT) {
            const float de = s_d[e];
            const int   ie = s_i[e];
            bool sel = true;
            if (count > 64) {
                int rank = 0;
                for (int j = 0; j < count; j++) {
                    float dj = s_d[j];
                    rank += (dj < de) || (dj == de && s_i[j] < ie);
                }
                sel = (rank < 64);
            }
            if (sel) {
                acc[3] += 1.0;                                        // pos
                acc[1] += (double)softplusf(-cls[(size_t)b * HW + ie]); // cls

                int ix = ie % Ws, iy = ie / Ws;
                float ax = (ix + 0.5f) * st;
                float ay = (iy + 0.5f) * st;
                float g0x = (Ax - ax) * inv, g0y = (Ay - ay) * inv;
                float g1x = (Bx - ax) * inv, g1y = (By - ay) * inv;
                float g2x = (Cx - ax) * inv, g2y = (Cy - ay) * inv;

                const float* rb = reg + (size_t)b * 6 * HW + ie;
                float p0x = fminf(fmaxf(rb[0],            -64.0f), 64.0f);
                float p0y = fminf(fmaxf(rb[(size_t)HW],   -64.0f), 64.0f);
                float p1x = fminf(fmaxf(rb[(size_t)2*HW], -64.0f), 64.0f);
                float p1y = fminf(fmaxf(rb[(size_t)3*HW], -64.0f), 64.0f);
                float p2x = fminf(fmaxf(rb[(size_t)4*HW], -64.0f), 64.0f);
                float p2y = fminf(fmaxf(rb[(size_t)5*HW], -64.0f), 64.0f);

                float p0 = (p0x - g0x) * (p0x - g0x) + (p0y - g0y) * (p0y - g0y);
                float d11 = sqrtf((p1x-g1x)*(p1x-g1x) + (p1y-g1y)*(p1y-g1y));
                float d12 = sqrtf((p1x-g2x)*(p1x-g2x) + (p1y-g2y)*(p1y-g2y));
                float d21 = sqrtf((p2x-g1x)*(p2x-g1x) + (p2y-g1y)*(p2y-g1y));
                float d22 = sqrtf((p2x-g2x)*(p2x-g2x) + (p2y-g2y)*(p2y-g2y));
                float cd = fminf(d11, d12) + fminf(d21, d22)
                         + fminf(d11, d21) + fminf(d12, d22);
                acc[0] += (double)(p0 + cd);                           // reg

                // obj correction, once per unique cell (atomicOr dedup)
                int cell = markBase + ie;
                unsigned bit = 1u << (cell & 31);
                unsigned old = atomicOr(&g_bits[cell >> 5], bit);
                if (!(old & bit)) {
                    float x = obj[(size_t)b * HW + ie];
                    float l1p = log1pf(expf(-fabsf(x)));
                    acc[2] += (double)(1.2f * (fmaxf(-x, 0.0f) + l1p)
                                       - (fmaxf(x, 0.0f) + l1p));
                    acc[4] += 1.0;                                     // posnow
                }
            }
        }
        __syncthreads();   // protect s_d/s_i/s_count before next task
    }

    // ---------------- Phase 1b: dense obj baseline ----------------
    for (int i = bid * NT + tid; i < TOTAL_CELLS; i += GRID * NT) {
        float x;
        if (i < 524288)      x = obj0[i];
        else if (i < 655360) x = obj1[i - 524288];
        else                 x = obj2[i - 655360];
        acc[2] += (double)(fmaxf(x, 0.0f) + log1pf(expf(-fabsf(x))));
    }

    // ---------------- block reduce -> per-block partials ----------------
#pragma unroll
    for (int c = 0; c < 5; c++) {
        s_red[tid] = acc[c];
        __syncthreads();
        for (int o = NT / 2; o > 0; o >>= 1) {
            if (tid < o) s_red[tid] += s_red[tid + o];
            __syncthreads();
        }
        if (tid == 0) g_part[bid][c] = s_red[0];
        __syncthreads();
    }

    // ---------------- grid barrier ----------------
    if (tid == 0) {
        __threadfence();
        atomicAdd(&g_arrive, 1);
        while (*(volatile int*)&g_arrive < GRID) __nanosleep(64);
        __threadfence();
    }
    __syncthreads();

    // ---------------- Phase 2: finalize + cleanup ----------------
    if (bid == 0) {
        double v[5];
#pragma unroll
        for (int c = 0; c < 5; c++) v[c] = 0.0;
        for (int i = tid; i < GRID; i += NT)
#pragma unroll
            for (int c = 0; c < 5; c++) v[c] += g_part[i][c];
#pragma unroll
        for (int c = 0; c < 5; c++) {
            s_red[tid] = v[c];
            __syncthreads();
            for (int o = NT / 2; o > 0; o >>= 1) {
                if (tid < o) s_red[tid] += s_red[tid + o];
                __syncthreads();
            }
            if (tid == 0) s_tot[c] = s_red[0];
            __syncthreads();
        }
        if (tid == 0) {
            double pos_eps = fmax(s_tot[3], 1.0);
            double neg = fmax((double)TOTAL_CELLS - s_tot[4], 1.0);
            double total = s_tot[0] / pos_eps
                         + s_tot[2] / (pos_eps + neg)
                         + s_tot[1] / pos_eps;
            float tt = (float)total;
            out[0] = isfinite(tt) ? tt : 0.0f;
        }
    } else {
        // clear dedup bitmask for the next graph replay
        for (int i = (bid - 1) * NT + tid; i < NBITS; i += (GRID - 1) * NT)
            g_bits[i] = 0u;
    }

    // ---------------- exit barrier: reset counters ----------------
    __syncthreads();
    if (tid == 0) {
        __threadfence();
        int r = atomicAdd(&g_exit, 1);
        if (r == GRID - 1) { g_task = 0; g_arrive = 0; g_exit = 0; }
    }
}

extern "C" void kernel_launch(void* const* d_in, const int* in_sizes, int n_in,
                              void* d_out, int out_size) {
    (void)in_sizes; (void)n_in; (void)out_size;
    fused_kernel<<<GRID, NT>>>(
        (const float*)d_in[0], (const float*)d_in[1], (const float*)d_in[2],
        (const float*)d_in[3], (const float*)d_in[4], (const float*)d_in[5],
        (const float*)d_in[6], (const float*)d_in[7], (const float*)d_in[8],
        (const float*)d_in[9], (float*)d_out);
}

// round 6
// speedup vs baseline: 1.5561x; 1.3979x over previous
#include <cuda_runtime.h>
#include <math.h>

// ----------------------------------------------------------------------------
// Strict2_5DLoss — single persistent kernel, v2.
// B=8, Ng=32, K=64, ETA=3, POS_W=1.2, strides {8,16,32}, grids {256,128,64}.
//
// One dynamic work queue: tasks 0..767 are (b,g,lvl) pair tasks (lvl0 first —
// LPT scheduling), tasks 768..935 are 4096-cell dense objectness chunks.
// Pair task: bbox scan on SQUARED segment distances (sqrt only for cells that
// pass a d^2 prefilter, so ranking ties match the reference's sqrt-rounded
// floats), positives packed as (dist_bits<<32)|idx u64 keys in smem, rank
// top-64 select, direct reg/cls/pos accumulation; objectness handled as a
// per-unique-cell correction via atomicOr-dedup bitmask.
// Grid barrier; block 0 reduces 592x5 partials + writes scalar; others clear
// the bitmask; exit barrier resets counters for graph replay determinism.
// ----------------------------------------------------------------------------

#define NT    256
#define GRID  592
#define CAP   2048
#define NPAIR 768
#define DCH   168                    // 168 * 4096 = 688128
#define NTASK (NPAIR + DCH)
#define TOTAL_CELLS 688128           // 8*(65536+16384+4096)
#define NBITS (TOTAL_CELLS / 32)

__device__ int g_task, g_arrive, g_exit;
__device__ unsigned g_bits[NBITS];   // zero-init at load; cleared every run
__device__ double g_part[GRID][5];   // reg, cls, obj, pos, posnow

// fast softplus: max(x,0) + log(1 + exp(-|x|)) via MUFU (abs err ~1e-7)
__device__ __forceinline__ float fast_sp(float x) {
    return fmaxf(x, 0.0f) + __logf(1.0f + __expf(-fabsf(x)));
}

__global__ void __launch_bounds__(NT, 4)
fused_kernel(const float* __restrict__ reg0, const float* __restrict__ obj0,
             const float* __restrict__ cls0,
             const float* __restrict__ reg1, const float* __restrict__ obj1,
             const float* __restrict__ cls1,
             const float* __restrict__ reg2, const float* __restrict__ obj2,
             const float* __restrict__ cls2,
             const float* __restrict__ gt, float* __restrict__ out) {
    __shared__ unsigned long long s_key[CAP];
    __shared__ int    s_task, s_count;
    __shared__ double s_w[8][5];

    const int tid  = threadIdx.x;
    const int bid  = blockIdx.x;
    const int wid  = tid >> 5;
    const int lane = tid & 31;

    double acc[5];  // 0:reg 1:cls 2:obj 3:pos 4:posnow
#pragma unroll
    for (int c = 0; c < 5; c++) acc[c] = 0.0;

    // ================= Phase 1: dynamic work queue =================
    for (;;) {
        if (tid == 0) { s_task = atomicAdd(&g_task, 1); s_count = 0; }
        __syncthreads();
        const int t = s_task;
        if (t >= NTASK) break;

        if (t >= NPAIR) {
            // ---- dense objectness baseline chunk (4096 cells) ----
            int base = (t - NPAIR) * 4096;
            const float* src; int off;
            if (base < 524288)      { src = obj0; off = base; }
            else if (base < 655360) { src = obj1; off = base - 524288; }
            else                    { src = obj2; off = base - 655360; }
            float fa = 0.0f;
#pragma unroll 4
            for (int k = tid; k < 4096; k += NT) {
                float x = src[off + k];
                fa += fmaxf(x, 0.0f) + __logf(1.0f + __expf(-fabsf(x)));
            }
            acc[2] += (double)fa;
            __syncthreads();
            continue;
        }

        // ---- pair task: lvl0 tasks first (t>>8 since NPAIR = 3*256) ----
        const int lvl = t >> 8;
        const int p   = t & 255;
        const int b   = p >> 5;
        const int g   = p & 31;
        const int lg  = 8 - lvl;
        const int Ws  = 1 << lg;
        const int HW  = Ws * Ws;
        const float st = (float)(8 << lvl);

        const float* reg = (lvl == 0) ? reg0 : (lvl == 1) ? reg1 : reg2;
        const float* cls = (lvl == 0) ? cls0 : (lvl == 1) ? cls1 : cls2;
        const float* obj = (lvl == 0) ? obj0 : (lvl == 1) ? obj1 : obj2;
        const int markBase =
            ((lvl == 0) ? 0 : (lvl == 1) ? 524288 : 655360) + b * HW;

        const float* gp = gt + (size_t)(b * 32 + g) * 6;
        const float Ax = gp[0], Ay = gp[1];
        const float Bx = gp[2], By = gp[3];
        const float Cx = gp[4], Cy = gp[5];

        // bbox expanded by ETA=3, over-covered by one cell
        float minx = fminf(Ax, fminf(Bx, Cx)) - 3.0f;
        float maxx = fmaxf(Ax, fmaxf(Bx, Cx)) + 3.0f;
        float miny = fminf(Ay, fminf(By, Cy)) - 3.0f;
        float maxy = fmaxf(Ay, fmaxf(By, Cy)) + 3.0f;
        int ix0 = max(0,      (int)floorf(minx / st - 0.5f));
        int ix1 = min(Ws - 1, (int)floorf(maxx / st - 0.5f) + 1);
        int iy0 = max(0,      (int)floorf(miny / st - 0.5f));
        int iy1 = min(Ws - 1, (int)floorf(maxy / st - 0.5f) + 1);
        int nx = ix1 - ix0 + 1; if (nx < 0) nx = 0;
        int ny = iy1 - iy0 + 1; if (ny < 0) ny = 0;
        const int tot = nx * ny;
        const float rnx = __fdividef(1.0f, (float)nx);

        // per-task edge precompute (reciprocal edge lengths hoisted)
        const float e0x = Bx - Ax, e0y = By - Ay;
        const float e1x = Cx - Bx, e1y = Cy - By;
        const float e2x = Ax - Cx, e2y = Ay - Cy;
        const float i0 = __fdividef(1.0f, e0x * e0x + e0y * e0y + 1e-9f);
        const float i1 = __fdividef(1.0f, e1x * e1x + e1y * e1y + 1e-9f);
        const float i2 = __fdividef(1.0f, e2x * e2x + e2y * e2y + 1e-9f);

        for (int c = tid; c < tot; c += NT) {
            int iy = (int)((float)c * rnx);
            int ix = c - iy * nx;
            if (ix < 0) { iy--; ix += nx; } else if (ix >= nx) { iy++; ix -= nx; }
            ix += ix0; iy += iy0;
            float px = (ix + 0.5f) * st;
            float py = (iy + 0.5f) * st;

            float d1 = (px - Bx) * (Ay - By) - (Ax - Bx) * (py - By);
            float d2 = (px - Cx) * (By - Cy) - (Bx - Cx) * (py - Cy);
            float d3 = (px - Ax) * (Cy - Ay) - (Cx - Ax) * (py - Ay);
            bool hneg = (d1 < 0.0f) || (d2 < 0.0f) || (d3 < 0.0f);
            bool hpos = (d1 > 0.0f) || (d2 > 0.0f) || (d3 > 0.0f);
            bool inside = !(hneg && hpos);

            // squared point-segment distances (no div, no sqrt)
            float wx = px - Ax, wy = py - Ay;
            float tt = fminf(fmaxf((wx * e0x + wy * e0y) * i0, 0.0f), 1.0f);
            float dx = wx - tt * e0x, dy = wy - tt * e0y;
            float dd = dx * dx + dy * dy;
            wx = px - Bx; wy = py - By;
            tt = fminf(fmaxf((wx * e1x + wy * e1y) * i1, 0.0f), 1.0f);
            dx = wx - tt * e1x; dy = wy - tt * e1y;
            dd = fminf(dd, dx * dx + dy * dy);
            wx = px - Cx; wy = py - Cy;
            tt = fminf(fmaxf((wx * e2x + wy * e2y) * i2, 0.0f), 1.0f);
            dx = wx - tt * e2x; dy = wy - tt * e2y;
            dd = fminf(dd, dx * dx + dy * dy);

            if (inside || dd <= 9.00001f) {       // prefilter with slack
                float dist = sqrtf(dd + 1e-12f);  // exact, matches reference
                if (inside || dist <= 3.0f) {
                    int slot = atomicAdd(&s_count, 1);
                    if (slot < CAP)
                        s_key[slot] =
                            ((unsigned long long)__float_as_uint(dist) << 32)
                            | (unsigned)(iy * Ws + ix);
                }
            }
        }
        __syncthreads();
        const int count = min(s_count, CAP);
        const float inv = 1.0f / st;    // power-of-two: exact

        float regA = 0.0f, clsA = 0.0f, objA = 0.0f;
        int nv = 0, nn = 0;

        for (int e = tid; e < count; e += NT) {
            const unsigned long long ke = s_key[e];
            bool sel = true;
            if (count > 64) {
                int rank = 0;
                for (int j = 0; j < count; j++) rank += (s_key[j] < ke);
                sel = (rank < 64);
            }
            if (sel) {
                const int ie = (int)(ke & 0xffffffffu);
                nv++;
                clsA += fast_sp(-cls[(size_t)b * HW + ie]);

                int ix = ie & (Ws - 1), iy = ie >> lg;
                float ax = (ix + 0.5f) * st;
                float ay = (iy + 0.5f) * st;
                float g0x = (Ax - ax) * inv, g0y = (Ay - ay) * inv;
                float g1x = (Bx - ax) * inv, g1y = (By - ay) * inv;
                float g2x = (Cx - ax) * inv, g2y = (Cy - ay) * inv;

                const float* rb = reg + (size_t)b * 6 * HW + ie;
                float p0x = fminf(fmaxf(rb[0],            -64.0f), 64.0f);
                float p0y = fminf(fmaxf(rb[(size_t)HW],   -64.0f), 64.0f);
                float p1x = fminf(fmaxf(rb[(size_t)2*HW], -64.0f), 64.0f);
                float p1y = fminf(fmaxf(rb[(size_t)3*HW], -64.0f), 64.0f);
                float p2x = fminf(fmaxf(rb[(size_t)4*HW], -64.0f), 64.0f);
                float p2y = fminf(fmaxf(rb[(size_t)5*HW], -64.0f), 64.0f);

                float p0 = (p0x - g0x) * (p0x - g0x) + (p0y - g0y) * (p0y - g0y);
                float d11 = sqrtf((p1x-g1x)*(p1x-g1x) + (p1y-g1y)*(p1y-g1y));
                float d12 = sqrtf((p1x-g2x)*(p1x-g2x) + (p1y-g2y)*(p1y-g2y));
                float d21 = sqrtf((p2x-g1x)*(p2x-g1x) + (p2y-g1y)*(p2y-g1y));
                float d22 = sqrtf((p2x-g2x)*(p2x-g2x) + (p2y-g2y)*(p2y-g2y));
                float cd = fminf(d11, d12) + fminf(d21, d22)
                         + fminf(d11, d21) + fminf(d12, d22);
                regA += p0 + cd;

                // objectness correction once per unique cell
                int cell = markBase + ie;
                unsigned bit = 1u << (cell & 31);
                unsigned old = atomicOr(&g_bits[cell >> 5], bit);
                if (!(old & bit)) {
                    float x = obj[(size_t)b * HW + ie];
                    objA += 1.2f * fast_sp(-x) - fast_sp(x);
                    nn++;
                }
            }
        }
        acc[0] += (double)regA;
        acc[1] += (double)clsA;
        acc[2] += (double)objA;
        acc[3] += (double)nv;
        acc[4] += (double)nn;
        __syncthreads();   // protect smem before next task fetch
    }

    // ================= block reduce -> per-block partials =================
#pragma unroll
    for (int c = 0; c < 5; c++) {
        double v = acc[c];
#pragma unroll
        for (int o = 16; o > 0; o >>= 1)
            v += __shfl_down_sync(0xffffffffu, v, o);
        if (lane == 0) s_w[wid][c] = v;
    }
    __syncthreads();
    if (wid == 0) {
#pragma unroll
        for (int c = 0; c < 5; c++) {
            double v = (lane < 8) ? s_w[lane][c] : 0.0;
#pragma unroll
            for (int o = 4; o > 0; o >>= 1)
                v += __shfl_down_sync(0xffffffffu, v, o);
            if (lane == 0) g_part[bid][c] = v;
        }
    }

    // ================= grid barrier =================
    if (tid == 0) {
        __threadfence();
        atomicAdd(&g_arrive, 1);
        while (*(volatile int*)&g_arrive < GRID) __nanosleep(64);
        __threadfence();
    }
    __syncthreads();

    // ================= Phase 2: finalize + cleanup =================
    if (bid == 0) {
        double v[5];
#pragma unroll
        for (int c = 0; c < 5; c++) v[c] = 0.0;
        for (int i = tid; i < GRID; i += NT)
#pragma unroll
            for (int c = 0; c < 5; c++) v[c] += g_part[i][c];
#pragma unroll
        for (int c = 0; c < 5; c++) {
            double r = v[c];
#pragma unroll
            for (int o = 16; o > 0; o >>= 1)
                r += __shfl_down_sync(0xffffffffu, r, o);
            if (lane == 0) s_w[wid][c] = r;
        }
        __syncthreads();
        if (tid == 0) {
            double tot[5];
#pragma unroll
            for (int c = 0; c < 5; c++) {
                double r = 0.0;
                for (int w = 0; w < 8; w++) r += s_w[w][c];
                tot[c] = r;
            }
            double pos_eps = fmax(tot[3], 1.0);
            double neg = fmax((double)TOTAL_CELLS - tot[4], 1.0);
            double total = tot[0] / pos_eps
                         + tot[2] / (pos_eps + neg)
                         + tot[1] / pos_eps;
            float tt = (float)total;
            out[0] = isfinite(tt) ? tt : 0.0f;
        }
    } else {
        for (int i = (bid - 1) * NT + tid; i < NBITS; i += (GRID - 1) * NT)
            g_bits[i] = 0u;
    }

    // ================= exit barrier: reset counters =================
    __syncthreads();
    if (tid == 0) {
        __threadfence();
        int r = atomicAdd(&g_exit, 1);
        if (r == GRID - 1) { g_task = 0; g_arrive = 0; g_exit = 0; }
    }
}

extern "C" void kernel_launch(void* const* d_in, const int* in_sizes, int n_in,
                              void* d_out, int out_size) {
    (void)in_sizes; (void)n_in; (void)out_size;
    fused_kernel<<<GRID, NT>>>(
        (const float*)d_in[0], (const float*)d_in[1], (const float*)d_in[2],
        (const float*)d_in[3], (const float*)d_in[4], (const float*)d_in[5],
        (const float*)d_in[6], (const float*)d_in[7], (const float*)d_in[8],
        (const float*)d_in[9], (float*)d_out);
}